// round 5
// baseline (speedup 1.0000x reference)
#include <cuda_runtime.h>
#include <math.h>

#define NA 10000
#define NE 320000
#define F  128
#define F3 (3*F)
#define NRBF 20
#define TT 3
#define ABI 16           // atoms/block: inter
#define API (ABI/2)
#define ABF 8            // atoms/block: field
#define APF (ABF/2)
#define ABM 8            // atoms/block: mix
#define APM (ABM/2)

typedef unsigned long long ull;

// ---------------- scratch (static device globals; no allocation) -------------
__device__ float g_q[NA*F];
__device__ float4 g_mu4[NA*F];     // mu interleaved: [N][F] -> (mu0,mu1,mu2,_)
__device__ float4 g_dmu4[NA*F];    // dmu interleaved
__device__ float4 g_x4[NA*F];      // x interleaved: (xq,xR,xM,_)
__device__ float g_E[NA*3];
__device__ float g_phi[NE*NRBF];   // phi * fcut, folded
__device__ float g_dir[NE*3];
__device__ float g_fcut[NE];
__device__ int   g_cnt[NA];
__device__ int   g_starts[NA+1];
__device__ int   g_cursor[NA];
__device__ int   g_perm[NE];

__device__ __forceinline__ float silu_f(float v) {
    return v * (1.0f / (1.0f + __expf(-v)));
}

// ---- packed f32x2 helpers (Blackwell; ptxas never emits FFMA2 from C++) ----
__device__ __forceinline__ ull pk2(float lo, float hi) {
    ull r; asm("mov.b64 %0, {%1,%2};" : "=l"(r) : "f"(lo), "f"(hi)); return r;
}
__device__ __forceinline__ void unpk2(ull v, float& lo, float& hi) {
    asm("mov.b64 {%0,%1}, %2;" : "=f"(lo), "=f"(hi) : "l"(v));
}
__device__ __forceinline__ ull ffma2(ull a, ull b, ull c) {
    ull d; asm("fma.rn.f32x2 %0, %1, %2, %3;" : "=l"(d) : "l"(a), "l"(b), "l"(c));
    return d;
}

// ---------------- init: q = emb[z], mu = 0, E per atom ----------------------
__global__ void k_init(const int* __restrict__ zn, const int* __restrict__ idx_m,
                       const float* __restrict__ e_field, const float* __restrict__ emb,
                       int n) {
    int i = blockIdx.x;
    int f = threadIdx.x;
    if (i >= n) return;
    int z = zn[i];
    g_q[i*F + f] = emb[z*F + f];
    g_mu4[(size_t)i*F + f] = make_float4(0.f, 0.f, 0.f, 0.f);
    if (f < 3) g_E[i*3 + f] = e_field[idx_m[i]*3 + f];
}

// ---------------- edge precompute: d, dir, fcut, phi*fcut -------------------
__global__ void k_edge(const float* __restrict__ r_ij, int ne) {
    int e = blockIdx.x * blockDim.x + threadIdx.x;
    if (e >= ne) return;
    float x0 = r_ij[e*3+0], x1 = r_ij[e*3+1], x2 = r_ij[e*3+2];
    float d = sqrtf(x0*x0 + x1*x1 + x2*x2);
    float inv = 1.0f / d;
    g_dir[e*3+0] = x0*inv;
    g_dir[e*3+1] = x1*inv;
    g_dir[e*3+2] = x2*inv;
    float fc = (d < 5.0f) ? 0.5f * (__cosf(d * 0.6283185307179586f) + 1.0f) : 0.0f;
    g_fcut[e] = fc;
    const float w    = 5.0f / 19.0f;
    const float invw = 19.0f / 5.0f;
    float ph[NRBF];
#pragma unroll
    for (int r = 0; r < NRBF; r++) {
        float t = (d - w * (float)r) * invw;
        ph[r] = __expf(-0.5f * t * t) * fc;
    }
    float4* dst = (float4*)(g_phi + (size_t)e * NRBF);
#pragma unroll
    for (int v = 0; v < 5; v++)
        dst[v] = make_float4(ph[4*v], ph[4*v+1], ph[4*v+2], ph[4*v+3]);
}

// ---------------- counting sort of edges by idx_i ---------------------------
__global__ void k_zero(int n) {
    int i = blockIdx.x * blockDim.x + threadIdx.x;
    if (i < n) g_cnt[i] = 0;
}
__global__ void k_hist(const int* __restrict__ idx_i, int ne) {
    int e = blockIdx.x * blockDim.x + threadIdx.x;
    if (e < ne) atomicAdd(&g_cnt[idx_i[e]], 1);
}
__global__ void k_scan(int n) {
    __shared__ int ss[1024];
    int tid = threadIdx.x;
    int chunk = (n + 1023) >> 10;
    int beg = tid * chunk;
    int end = min(beg + chunk, n);
    int s = 0;
    for (int i = beg; i < end; i++) s += g_cnt[i];
    ss[tid] = s;
    __syncthreads();
    for (int off = 1; off < 1024; off <<= 1) {
        int v = (tid >= off) ? ss[tid - off] : 0;
        __syncthreads();
        ss[tid] += v;
        __syncthreads();
    }
    int base = (tid == 0) ? 0 : ss[tid - 1];
    for (int i = beg; i < end; i++) {
        g_starts[i] = base;
        g_cursor[i] = base;
        base += g_cnt[i];
    }
    if (tid == 1023) g_starts[n] = ss[1023];
}
__global__ void k_scatter(const int* __restrict__ idx_i, int ne) {
    int e = blockIdx.x * blockDim.x + threadIdx.x;
    if (e < ne) {
        int p = atomicAdd(&g_cursor[idx_i[e]], 1);
        g_perm[p] = e;
    }
}

// ---------------- inter: x = silu(q@W1+b1)@W2+b2  (A=16, f32x2-packed) -----
__global__ void __launch_bounds__(128) k_inter(
        const float* __restrict__ W1, const float* __restrict__ b1,
        const float* __restrict__ W2, const float* __restrict__ b2, int n) {
    __shared__ float sq[F][ABI];         // sq[k][a]; reused for h after stage 1
    int f = threadIdx.x;
    int a0 = blockIdx.x * ABI;
#pragma unroll
    for (int a = 0; a < ABI; a++) {
        int at = a0 + a;
        int atc = (at < n) ? at : 0;
        sq[f][a] = g_q[atc*F + f];
    }
    __syncthreads();
    // stage 1: h = silu(q @ W1 + b1)
    ull acc[API];
    {
        float bb = b1[f];
        ull bb2 = pk2(bb, bb);
#pragma unroll
        for (int p = 0; p < API; p++) acc[p] = bb2;
#pragma unroll 4
        for (int k = 0; k < F; k++) {
            float w = W1[k*F + f];
            ull w2 = pk2(w, w);
            const ull* row = (const ull*)sq[k];
#pragma unroll
            for (int p = 0; p < API; p++) acc[p] = ffma2(row[p], w2, acc[p]);
        }
    }
    __syncthreads();
#pragma unroll
    for (int p = 0; p < API; p++) {
        float lo, hi; unpk2(acc[p], lo, hi);
        sq[f][2*p]   = silu_f(lo);
        sq[f][2*p+1] = silu_f(hi);
    }
    __syncthreads();
    // stage 2: x = h @ W2 + b2 (3 output chunks -> interleaved scalar stores)
    float* x4f = (float*)g_x4;
#pragma unroll
    for (int c = 0; c < 3; c++) {
        float cb = b2[c*F + f];
        ull acc2[API];
        ull cb2 = pk2(cb, cb);
#pragma unroll
        for (int p = 0; p < API; p++) acc2[p] = cb2;
#pragma unroll 4
        for (int k = 0; k < F; k++) {
            float w = W2[k*F3 + c*F + f];
            ull w2 = pk2(w, w);
            const ull* row = (const ull*)sq[k];
#pragma unroll
            for (int p = 0; p < API; p++) acc2[p] = ffma2(row[p], w2, acc2[p]);
        }
#pragma unroll
        for (int p = 0; p < API; p++) {
            float lo, hi; unpk2(acc2[p], lo, hi);
            int at = a0 + 2*p;
            if (at < n)     x4f[((size_t)at*F + f)*4 + c]     = lo;
            if (at + 1 < n) x4f[((size_t)(at+1)*F + f)*4 + c] = hi;
        }
    }
}

// ---------------- message passing (one block per destination atom) ---------
// float4 gathers (x, mu interleaved) + software-pipelined edge loop.
__global__ void __launch_bounds__(128) k_msg(
        const float* __restrict__ filt_W, const float* __restrict__ filt_b,
        const int* __restrict__ idx_j, int t, int n) {
    __shared__ float sphi[128 * NRBF];
    __shared__ int   sj[128];
    __shared__ float sfc[128], sd0[128], sd1[128], sd2[128];
    int i = blockIdx.x;
    int f = threadIdx.x;

    ull wq2[NRBF/2], wR2[NRBF/2], wM2[NRBF/2];
#pragma unroll
    for (int m = 0; m < NRBF/2; m++) {
        const float* base = filt_W + (2*m) * (TT*F3) + t*F3;
        float aq = base[f],        bqv = base[TT*F3 + f];
        float aR = base[F + f],    bRv = base[TT*F3 + F + f];
        float aM = base[2*F + f],  bMv = base[TT*F3 + 2*F + f];
        wq2[m] = pk2(aq, bqv);
        wR2[m] = pk2(aR, bRv);
        wM2[m] = pk2(aM, bMv);
    }
    float bq = filt_b[t*F3 + f];
    float bR = filt_b[t*F3 + F + f];
    float bM = filt_b[t*F3 + 2*F + f];

    if (i >= n) return;
    int nb = g_starts[i], nend = g_starts[i+1];
    float dq = 0.0f, dm0 = 0.0f, dm1 = 0.0f, dm2 = 0.0f;

    for (int base = nb; base < nend; base += 128) {
        int cnt = min(128, nend - base);
        __syncthreads();
        if (f < cnt) {
            int e = g_perm[base + f];
            sj[f]  = idx_j[e];
            sfc[f] = g_fcut[e];
            sd0[f] = g_dir[e*3+0];
            sd1[f] = g_dir[e*3+1];
            sd2[f] = g_dir[e*3+2];
            const float4* pp = (const float4*)(g_phi + (size_t)e * NRBF);
            float4* dst = (float4*)(sphi + f * NRBF);
#pragma unroll
            for (int v = 0; v < 5; v++) dst[v] = pp[v];
        }
        __syncthreads();
        // prefetch edge 0
        int j0 = sj[0];
        float4 xv = g_x4[(size_t)j0*F + f];
        float4 mv = g_mu4[(size_t)j0*F + f];
        for (int k = 0; k < cnt; k++) {
            // prefetch edge k+1 (clamped; redundant on last iter, branch-free)
            int kn = (k + 1 < cnt) ? k + 1 : k;
            int jn = sj[kn];
            float4 xn = g_x4[(size_t)jn*F + f];
            float4 mn = g_mu4[(size_t)jn*F + f];

            float fc = sfc[k];
            ull accq = pk2(bq * fc, 0.0f);
            ull accR = pk2(bR * fc, 0.0f);
            ull accM = pk2(bM * fc, 0.0f);
            const ull* p2 = (const ull*)(sphi + k * NRBF);
#pragma unroll
            for (int m = 0; m < NRBF/2; m++) {
                ull pp = p2[m];
                accq = ffma2(pp, wq2[m], accq);
                accR = ffma2(pp, wR2[m], accR);
                accM = ffma2(pp, wM2[m], accM);
            }
            float ql, qh, Rl, Rh, Ml, Mh;
            unpk2(accq, ql, qh);
            unpk2(accR, Rl, Rh);
            unpk2(accM, Ml, Mh);
            float fq = ql + qh, fR = Rl + Rh, fM = Ml + Mh;

            dq = fmaf(fq, xv.x, dq);
            float dR = fR * xv.y;
            float dM = fM * xv.z;
            dm0 = fmaf(dR, sd0[k], fmaf(dM, mv.x, dm0));
            dm1 = fmaf(dR, sd1[k], fmaf(dM, mv.y, dm1));
            dm2 = fmaf(dR, sd2[k], fmaf(dM, mv.z, dm2));

            xv = xn; mv = mn;
        }
    }
    g_q[i*F + f] += dq;
    g_dmu4[(size_t)i*F + f] = make_float4(dm0, dm1, dm2, 0.f);
}

// ---------------- field interaction (A=8, folds dmu) ------------------------
__global__ void __launch_bounds__(128) k_field(
        const float* __restrict__ sW1, const float* __restrict__ sb1,
        const float* __restrict__ sW2, const float* __restrict__ sb2,
        const float* __restrict__ vW, int n) {
    __shared__ float sq[F][ABF];         // q; reused for h
    __shared__ float smu[3][F][ABF];     // mu + dmu
    __shared__ float sE[ABF][3];
    int f = threadIdx.x;
    int a0 = blockIdx.x * ABF;
#pragma unroll
    for (int a = 0; a < ABF; a++) {
        int at = a0 + a;
        int atc = (at < n) ? at : 0;
        sq[f][a] = g_q[atc*F + f];
        float4 m4 = g_mu4[(size_t)atc*F + f];
        float4 d4 = g_dmu4[(size_t)atc*F + f];
        smu[0][f][a] = m4.x + d4.x;
        smu[1][f][a] = m4.y + d4.y;
        smu[2][f][a] = m4.z + d4.z;
    }
    if (f < ABF*3) {
        int a = f / 3, c = f % 3;
        int at = a0 + a;
        sE[a][c] = (at < n) ? g_E[at*3 + c] : 0.0f;
    }
    __syncthreads();
    // stage 1: h = silu(q @ sW1 + sb1)
    ull acc[APF];
    {
        float bb = sb1[f];
        ull bb2 = pk2(bb, bb);
#pragma unroll
        for (int p = 0; p < APF; p++) acc[p] = bb2;
#pragma unroll 4
        for (int k = 0; k < F; k++) {
            float w = sW1[k*F + f];
            ull w2 = pk2(w, w);
            const ull* row = (const ull*)sq[k];
#pragma unroll
            for (int p = 0; p < APF; p++) acc[p] = ffma2(row[p], w2, acc[p]);
        }
    }
    __syncthreads();
#pragma unroll
    for (int p = 0; p < APF; p++) {
        float lo, hi; unpk2(acc[p], lo, hi);
        sq[f][2*p]   = silu_f(lo);
        sq[f][2*p+1] = silu_f(hi);
    }
    __syncthreads();
    // stage 2: a_s = h @ sW2 + sb2
    ull as2[APF];
    {
        float bb = sb2[f];
        ull bb2 = pk2(bb, bb);
#pragma unroll
        for (int p = 0; p < APF; p++) as2[p] = bb2;
#pragma unroll 4
        for (int k = 0; k < F; k++) {
            float w = sW2[k*F + f];
            ull w2 = pk2(w, w);
            const ull* row = (const ull*)sq[k];
#pragma unroll
            for (int p = 0; p < APF; p++) as2[p] = ffma2(row[p], w2, as2[p]);
        }
    }
    // stage 3: a_v = mu @ vW
    ull av2[3][APF];
#pragma unroll
    for (int kv = 0; kv < 3; kv++)
#pragma unroll
        for (int p = 0; p < APF; p++) av2[kv][p] = 0ull;
#pragma unroll 2
    for (int c = 0; c < F; c++) {
        float w = vW[c*F + f];
        ull w2 = pk2(w, w);
#pragma unroll
        for (int kv = 0; kv < 3; kv++) {
            const ull* row = (const ull*)smu[kv][c];
#pragma unroll
            for (int p = 0; p < APF; p++) av2[kv][p] = ffma2(row[p], w2, av2[kv][p]);
        }
    }
    // epilogue -> float4 stores
#pragma unroll
    for (int p = 0; p < APF; p++) {
        float as_l, as_h; unpk2(as2[p], as_l, as_h);
        float a0l, a0h, a1l, a1h, a2l, a2h;
        unpk2(av2[0][p], a0l, a0h);
        unpk2(av2[1][p], a1l, a1h);
        unpk2(av2[2][p], a2l, a2h);
#pragma unroll
        for (int lane = 0; lane < 2; lane++) {
            int a = 2*p + lane;
            int at = a0 + a;
            if (at >= n) continue;
            float asv = lane ? as_h : as_l;
            float v0 = lane ? a0h : a0l;
            float v1 = lane ? a1h : a1l;
            float v2 = lane ? a2h : a2l;
            float E0 = sE[a][0], E1 = sE[a][1], E2 = sE[a][2];
            float dot = v0*E0 + v1*E1 + v2*E2;
            g_mu4[(size_t)at*F + f] = make_float4(
                smu[0][f][a] + asv*E0 - dot*v0,
                smu[1][f][a] + asv*E1 - dot*v1,
                smu[2][f][a] + asv*E2 - dot*v2, 0.f);
        }
    }
}

// ---------------- mixing (A=8) ----------------------------------------------
__global__ void __launch_bounds__(128) k_mix(
        const float* __restrict__ muW, const float* __restrict__ W1,
        const float* __restrict__ b1,  const float* __restrict__ W2,
        const float* __restrict__ b2,  int n) {
    __shared__ float smu[3][F][ABM];     // 12 KB
    __shared__ float cs[2*F][ABM];       // 8 KB
    int f = threadIdx.x;
    int a0 = blockIdx.x * ABM;
#pragma unroll
    for (int a = 0; a < ABM; a++) {
        int at = a0 + a;
        int atc = (at < n) ? at : 0;
        cs[f][a] = g_q[atc*F + f];
        float4 m4 = g_mu4[(size_t)atc*F + f];
        smu[0][f][a] = m4.x;
        smu[1][f][a] = m4.y;
        smu[2][f][a] = m4.z;
    }
    __syncthreads();
    ull Wc2[3][APM];
    ull sdot2[APM];
    {
        ull V2[3][APM];
#pragma unroll
        for (int kv = 0; kv < 3; kv++)
#pragma unroll
            for (int p = 0; p < APM; p++) { V2[kv][p] = 0ull; Wc2[kv][p] = 0ull; }
#pragma unroll 2
        for (int c = 0; c < F; c++) {
            float wv = muW[c*2*F + f];
            float ww = muW[c*2*F + F + f];
            ull wv2 = pk2(wv, wv);
            ull ww2 = pk2(ww, ww);
#pragma unroll
            for (int kv = 0; kv < 3; kv++) {
                const ull* row = (const ull*)smu[kv][c];
#pragma unroll
                for (int p = 0; p < APM; p++) {
                    ull m = row[p];
                    V2[kv][p]  = ffma2(m, wv2, V2[kv][p]);
                    Wc2[kv][p] = ffma2(m, ww2, Wc2[kv][p]);
                }
            }
        }
#pragma unroll
        for (int p = 0; p < APM; p++) {
            float v0l, v0h, v1l, v1h, v2l, v2h;
            unpk2(V2[0][p], v0l, v0h);
            unpk2(V2[1][p], v1l, v1h);
            unpk2(V2[2][p], v2l, v2h);
            float w0l, w0h, w1l, w1h, w2l, w2h;
            unpk2(Wc2[0][p], w0l, w0h);
            unpk2(Wc2[1][p], w1l, w1h);
            unpk2(Wc2[2][p], w2l, w2h);
            float vnl = sqrtf(v0l*v0l + v1l*v1l + v2l*v2l + 1e-8f);
            float vnh = sqrtf(v0h*v0h + v1h*v1h + v2h*v2h + 1e-8f);
            cs[F + f][2*p]   = vnl;
            cs[F + f][2*p+1] = vnh;
            sdot2[p] = pk2(v0l*w0l + v1l*w1l + v2l*w2l,
                           v0h*w0h + v1h*w1h + v2h*w2h);
        }
    }
    __syncthreads();
    // stage B: h = silu(ctx @ W1 + b1), ctx dim = 2F
    ull acc[APM];
    {
        float bb = b1[f];
        ull bb2 = pk2(bb, bb);
#pragma unroll
        for (int p = 0; p < APM; p++) acc[p] = bb2;
#pragma unroll 4
        for (int k = 0; k < 2*F; k++) {
            float w = W1[k*F + f];
            ull w2 = pk2(w, w);
            const ull* row = (const ull*)cs[k];
#pragma unroll
            for (int p = 0; p < APM; p++) acc[p] = ffma2(row[p], w2, acc[p]);
        }
    }
    __syncthreads();
#pragma unroll
    for (int p = 0; p < APM; p++) {
        float lo, hi; unpk2(acc[p], lo, hi);
        cs[f][2*p]   = silu_f(lo);
        cs[f][2*p+1] = silu_f(hi);
    }
    __syncthreads();
    // stage C
    ull y0_2[APM];
#pragma unroll
    for (int c = 0; c < 3; c++) {
        float cb = b2[c*F + f];
        ull accY[APM];
        ull cb2 = pk2(cb, cb);
#pragma unroll
        for (int p = 0; p < APM; p++) accY[p] = cb2;
#pragma unroll 4
        for (int k = 0; k < F; k++) {
            float w = W2[k*F3 + c*F + f];
            ull w2 = pk2(w, w);
            const ull* row = (const ull*)cs[k];
#pragma unroll
            for (int p = 0; p < APM; p++) accY[p] = ffma2(row[p], w2, accY[p]);
        }
        if (c == 0) {
#pragma unroll
            for (int p = 0; p < APM; p++) y0_2[p] = accY[p];
        } else if (c == 1) {
#pragma unroll
            for (int p = 0; p < APM; p++) {
                float y1l, y1h; unpk2(accY[p], y1l, y1h);
                float w0l, w0h, w1l, w1h, w2l, w2h;
                unpk2(Wc2[0][p], w0l, w0h);
                unpk2(Wc2[1][p], w1l, w1h);
                unpk2(Wc2[2][p], w2l, w2h);
                int at = a0 + 2*p;
                if (at < n)
                    g_mu4[(size_t)at*F + f] = make_float4(
                        smu[0][f][2*p] + y1l*w0l,
                        smu[1][f][2*p] + y1l*w1l,
                        smu[2][f][2*p] + y1l*w2l, 0.f);
                if (at + 1 < n)
                    g_mu4[(size_t)(at+1)*F + f] = make_float4(
                        smu[0][f][2*p+1] + y1h*w0h,
                        smu[1][f][2*p+1] + y1h*w1h,
                        smu[2][f][2*p+1] + y1h*w2h, 0.f);
            }
        } else {
#pragma unroll
            for (int p = 0; p < APM; p++) {
                float y2l, y2h; unpk2(accY[p], y2l, y2h);
                float y0l, y0h; unpk2(y0_2[p], y0l, y0h);
                float sdl, sdh; unpk2(sdot2[p], sdl, sdh);
                int at = a0 + 2*p;
                if (at < n)     g_q[(size_t)at*F + f]     += y0l + y2l*sdl;
                if (at + 1 < n) g_q[(size_t)(at+1)*F + f] += y0h + y2h*sdh;
            }
        }
    }
}

// ---------------- pack output [N,4,F] ---------------------------------------
__global__ void k_pack(float* __restrict__ out, int n) {
    int i = blockIdx.x;
    int f = threadIdx.x;
    if (i >= n) return;
    out[i*4*F + f] = g_q[i*F + f];
    float4 m4 = g_mu4[(size_t)i*F + f];
    out[i*4*F + F + f]   = m4.x;
    out[i*4*F + 2*F + f] = m4.y;
    out[i*4*F + 3*F + f] = m4.z;
}

// ---------------- launch -----------------------------------------------------
extern "C" void kernel_launch(void* const* d_in, const int* in_sizes, int n_in,
                              void* d_out, int out_size) {
    const int*   zn      = (const int*)  d_in[0];
    const float* r_ij    = (const float*)d_in[1];
    const int*   idx_i   = (const int*)  d_in[2];
    const int*   idx_j   = (const int*)  d_in[3];
    const int*   idx_m   = (const int*)  d_in[4];
    const float* e_field = (const float*)d_in[5];
    const float* emb     = (const float*)d_in[6];
    const float* filt_W  = (const float*)d_in[7];
    const float* filt_b  = (const float*)d_in[8];
    const float* iW1     = (const float*)d_in[9];
    const float* ib1     = (const float*)d_in[10];
    const float* iW2     = (const float*)d_in[11];
    const float* ib2     = (const float*)d_in[12];
    const float* fsW1    = (const float*)d_in[13];
    const float* fsb1    = (const float*)d_in[14];
    const float* fsW2    = (const float*)d_in[15];
    const float* fsb2    = (const float*)d_in[16];
    const float* fvW     = (const float*)d_in[17];
    const float* mmuW    = (const float*)d_in[18];
    const float* mW1     = (const float*)d_in[19];
    const float* mb1     = (const float*)d_in[20];
    const float* mW2     = (const float*)d_in[21];
    const float* mb2     = (const float*)d_in[22];

    int n  = in_sizes[0];   // 10000
    int ne = in_sizes[2];   // 320000
    int nblkI = (n + ABI - 1) / ABI;
    int nblkF = (n + ABF - 1) / ABF;
    int nblkM = (n + ABM - 1) / ABM;

    k_init<<<n, F>>>(zn, idx_m, e_field, emb, n);
    k_edge<<<(ne + 255) / 256, 256>>>(r_ij, ne);
    k_zero<<<(n + 255) / 256, 256>>>(n);
    k_hist<<<(ne + 255) / 256, 256>>>(idx_i, ne);
    k_scan<<<1, 1024>>>(n);
    k_scatter<<<(ne + 255) / 256, 256>>>(idx_i, ne);

    for (int t = 0; t < TT; t++) {
        k_inter<<<nblkI, F>>>(iW1 + t*F*F, ib1 + t*F,
                              iW2 + t*F*F3, ib2 + t*F3, n);
        k_msg<<<n, F>>>(filt_W, filt_b, idx_j, t, n);
        k_field<<<nblkF, F>>>(fsW1 + t*F*F, fsb1 + t*F,
                              fsW2 + t*F*F, fsb2 + t*F,
                              fvW + t*F*F, n);
        k_mix<<<nblkM, F>>>(mmuW + t*F*2*F, mW1 + t*2*F*F, mb1 + t*F,
                            mW2 + t*F*F3, mb2 + t*F3, n);
    }
    k_pack<<<n, F>>>((float*)d_out, n);
}

// round 6
// speedup vs baseline: 1.2560x; 1.2560x over previous
#include <cuda_runtime.h>
#include <math.h>

#define NA 10000
#define NE 320000
#define F  128
#define F3 (3*F)
#define NRBF 20
#define TT 3
#define NK 2048          // table rows per t (pairs k=0..2046 used)
#define ABI 16
#define API (ABI/2)
#define ABF 8
#define APF (ABF/2)
#define ABM 8
#define APM (ABM/2)

typedef unsigned long long ull;

// ---------------- scratch (static device globals; no allocation) -------------
__device__ float g_q[NA*F];
__device__ float g_mu[NA*F3];
__device__ float g_dmu[NA*F3];
__device__ float g_E[NA*3];
__device__ float g_x[NA*F3];
__device__ float2 g_tabP[TT*NK*F3];  // filter table pairs: (v[k],v[k+1]) per channel
__device__ float g_dir[NE*3];
__device__ int   g_k0[NE];
__device__ float g_fr[NE];
__device__ int   g_cnt[NA];
__device__ int   g_starts[NA+1];
__device__ int   g_cursor[NA];
__device__ int   g_perm[NE];

__device__ __forceinline__ float silu_f(float v) {
    return v * (1.0f / (1.0f + __expf(-v)));
}

// ---- packed f32x2 helpers ----
__device__ __forceinline__ ull pk2(float lo, float hi) {
    ull r; asm("mov.b64 %0, {%1,%2};" : "=l"(r) : "f"(lo), "f"(hi)); return r;
}
__device__ __forceinline__ void unpk2(ull v, float& lo, float& hi) {
    asm("mov.b64 {%0,%1}, %2;" : "=f"(lo), "=f"(hi) : "l"(v));
}
__device__ __forceinline__ ull ffma2(ull a, ull b, ull c) {
    ull d; asm("fma.rn.f32x2 %0, %1, %2, %3;" : "=l"(d) : "l"(a), "l"(b), "l"(c));
    return d;
}

// ---------------- init ------------------------------------------------------
__global__ void k_init(const int* __restrict__ zn, const int* __restrict__ idx_m,
                       const float* __restrict__ e_field, const float* __restrict__ emb,
                       int n) {
    int i = blockIdx.x;
    int f = threadIdx.x;
    if (i >= n) return;
    int z = zn[i];
    g_q[i*F + f] = emb[z*F + f];
    g_mu[i*F3 + f]       = 0.0f;
    g_mu[i*F3 + F + f]   = 0.0f;
    g_mu[i*F3 + 2*F + f] = 0.0f;
    if (f < 3) g_E[i*3 + f] = e_field[idx_m[i]*3 + f];
}

// ---------------- edge precompute: dir, table coords ------------------------
__global__ void k_edge(const float* __restrict__ r_ij, int ne) {
    int e = blockIdx.x * blockDim.x + threadIdx.x;
    if (e >= ne) return;
    float x0 = r_ij[e*3+0], x1 = r_ij[e*3+1], x2 = r_ij[e*3+2];
    float d = sqrtf(x0*x0 + x1*x1 + x2*x2);
    float inv = 1.0f / d;
    g_dir[e*3+0] = x0*inv;
    g_dir[e*3+1] = x1*inv;
    g_dir[e*3+2] = x2*inv;
    float u = d * ((float)(NK-1) / 5.0f);      // 2047/5
    u = fminf(u, (float)(NK-1));               // d>=5 -> u=2047 -> v[2047]=0
    int k0 = min((int)u, NK-2);
    g_k0[e] = k0;
    g_fr[e] = u - (float)k0;
}

// ---------------- filter table build ----------------------------------------
// block b: t = b/(NK-1), k = b%(NK-1); computes pair (knot k, knot k+1) for all 384 ch
__global__ void k_tab(const float* __restrict__ filt_W, const float* __restrict__ filt_b) {
    __shared__ float ph[2][NRBF];
    __shared__ float fcs[2];
    int b = blockIdx.x;
    int t = b / (NK-1);
    int k = b % (NK-1);
    int c = threadIdx.x;  // 0..383
    const float h = 5.0f / (float)(NK-1);
    const float w = 5.0f / 19.0f;
    if (c < 2*NRBF) {
        int s = c / NRBF, r = c % NRBF;
        float d = (float)(k + s) * h;
        float tt = (d - w * (float)r) / w;
        ph[s][r] = __expf(-0.5f * tt * tt);
    }
    if (c >= 2*NRBF && c < 2*NRBF + 2) {
        int s = c - 2*NRBF;
        int kk = k + s;
        float d = (float)kk * h;
        fcs[s] = (kk >= NK-1) ? 0.0f : 0.5f * (__cosf(d * 0.6283185307179586f) + 1.0f);
    }
    __syncthreads();
    float bb = filt_b[t*F3 + c];
    float a0 = bb, a1 = bb;
#pragma unroll
    for (int r = 0; r < NRBF; r++) {
        float wv = filt_W[r * (TT*F3) + t*F3 + c];
        a0 = fmaf(ph[0][r], wv, a0);
        a1 = fmaf(ph[1][r], wv, a1);
    }
    g_tabP[((size_t)(t*NK + k))*F3 + c] = make_float2(a0 * fcs[0], a1 * fcs[1]);
}

// ---------------- counting sort of edges by idx_i ---------------------------
__global__ void k_zero(int n) {
    int i = blockIdx.x * blockDim.x + threadIdx.x;
    if (i < n) g_cnt[i] = 0;
}
__global__ void k_hist(const int* __restrict__ idx_i, int ne) {
    int e = blockIdx.x * blockDim.x + threadIdx.x;
    if (e < ne) atomicAdd(&g_cnt[idx_i[e]], 1);
}
__global__ void k_scan(int n) {
    __shared__ int ss[1024];
    int tid = threadIdx.x;
    int chunk = (n + 1023) >> 10;
    int beg = tid * chunk;
    int end = min(beg + chunk, n);
    int s = 0;
    for (int i = beg; i < end; i++) s += g_cnt[i];
    ss[tid] = s;
    __syncthreads();
    for (int off = 1; off < 1024; off <<= 1) {
        int v = (tid >= off) ? ss[tid - off] : 0;
        __syncthreads();
        ss[tid] += v;
        __syncthreads();
    }
    int base = (tid == 0) ? 0 : ss[tid - 1];
    for (int i = beg; i < end; i++) {
        g_starts[i] = base;
        g_cursor[i] = base;
        base += g_cnt[i];
    }
    if (tid == 1023) g_starts[n] = ss[1023];
}
__global__ void k_scatter(const int* __restrict__ idx_i, int ne) {
    int e = blockIdx.x * blockDim.x + threadIdx.x;
    if (e < ne) {
        int p = atomicAdd(&g_cursor[idx_i[e]], 1);
        g_perm[p] = e;
    }
}

// ---------------- inter: x = silu(q@W1+b1)@W2+b2  (A=16, f32x2) ------------
__global__ void __launch_bounds__(128) k_inter(
        const float* __restrict__ W1, const float* __restrict__ b1,
        const float* __restrict__ W2, const float* __restrict__ b2, int n) {
    __shared__ float sq[F][ABI];
    int f = threadIdx.x;
    int a0 = blockIdx.x * ABI;
#pragma unroll
    for (int a = 0; a < ABI; a++) {
        int at = a0 + a;
        int atc = (at < n) ? at : 0;
        sq[f][a] = g_q[atc*F + f];
    }
    __syncthreads();
    ull acc[API];
    {
        float bb = b1[f];
        ull bb2 = pk2(bb, bb);
#pragma unroll
        for (int p = 0; p < API; p++) acc[p] = bb2;
#pragma unroll 4
        for (int k = 0; k < F; k++) {
            float w = W1[k*F + f];
            ull w2 = pk2(w, w);
            const ull* row = (const ull*)sq[k];
#pragma unroll
            for (int p = 0; p < API; p++) acc[p] = ffma2(row[p], w2, acc[p]);
        }
    }
    __syncthreads();
#pragma unroll
    for (int p = 0; p < API; p++) {
        float lo, hi; unpk2(acc[p], lo, hi);
        sq[f][2*p]   = silu_f(lo);
        sq[f][2*p+1] = silu_f(hi);
    }
    __syncthreads();
#pragma unroll
    for (int c = 0; c < 3; c++) {
        float cb = b2[c*F + f];
        ull acc2[API];
        ull cb2 = pk2(cb, cb);
#pragma unroll
        for (int p = 0; p < API; p++) acc2[p] = cb2;
#pragma unroll 4
        for (int k = 0; k < F; k++) {
            float w = W2[k*F3 + c*F + f];
            ull w2 = pk2(w, w);
            const ull* row = (const ull*)sq[k];
#pragma unroll
            for (int p = 0; p < API; p++) acc2[p] = ffma2(row[p], w2, acc2[p]);
        }
#pragma unroll
        for (int p = 0; p < API; p++) {
            float lo, hi; unpk2(acc2[p], lo, hi);
            int at = a0 + 2*p;
            if (at < n)     g_x[(size_t)at*F3 + c*F + f]     = lo;
            if (at + 1 < n) g_x[(size_t)(at+1)*F3 + c*F + f] = hi;
        }
    }
}

// ---------------- message passing: table-interp filters ---------------------
__global__ void __launch_bounds__(128) k_msg(
        const int* __restrict__ idx_j, int t, int n) {
    __shared__ int   sj[128], sk0[128];
    __shared__ float sfr[128], sd0[128], sd1[128], sd2[128];
    int i = blockIdx.x;
    int f = threadIdx.x;
    if (i >= n) return;
    const float2* __restrict__ tabT = g_tabP + (size_t)t * NK * F3;
    int nb = g_starts[i], nend = g_starts[i+1];
    float dq = 0.0f, dm0 = 0.0f, dm1 = 0.0f, dm2 = 0.0f;

    for (int base = nb; base < nend; base += 128) {
        int cnt = min(128, nend - base);
        __syncthreads();
        if (f < cnt) {
            int e = g_perm[base + f];
            sj[f]  = idx_j[e];
            sk0[f] = g_k0[e];
            sfr[f] = g_fr[e];
            sd0[f] = g_dir[e*3+0];
            sd1[f] = g_dir[e*3+1];
            sd2[f] = g_dir[e*3+2];
        }
        __syncthreads();
        for (int k = 0; k < cnt; k++) {
            int j = sj[k];
            const float2* tr = tabT + (size_t)sk0[k] * F3;   // warp-uniform row
            float fr = sfr[k];
            float2 vq = tr[f];
            float2 vR = tr[F + f];
            float2 vM = tr[2*F + f];
            const float* xr = g_x  + (size_t)j * F3;
            const float* mr = g_mu + (size_t)j * F3;
            float xq = xr[f], xR = xr[F + f], xM = xr[2*F + f];
            float m0 = mr[f], m1 = mr[F + f], m2 = mr[2*F + f];

            float fq = fmaf(fr, vq.y - vq.x, vq.x);
            float fR = fmaf(fr, vR.y - vR.x, vR.x);
            float fM = fmaf(fr, vM.y - vM.x, vM.x);

            dq = fmaf(fq, xq, dq);
            float dR = fR * xR;
            float dM = fM * xM;
            dm0 = fmaf(dR, sd0[k], fmaf(dM, m0, dm0));
            dm1 = fmaf(dR, sd1[k], fmaf(dM, m1, dm1));
            dm2 = fmaf(dR, sd2[k], fmaf(dM, m2, dm2));
        }
    }
    g_q[i*F + f] += dq;
    g_dmu[i*F3 + f]       = dm0;
    g_dmu[i*F3 + F + f]   = dm1;
    g_dmu[i*F3 + 2*F + f] = dm2;
}

// ---------------- field interaction (A=8, folds dmu) ------------------------
__global__ void __launch_bounds__(128) k_field(
        const float* __restrict__ sW1, const float* __restrict__ sb1,
        const float* __restrict__ sW2, const float* __restrict__ sb2,
        const float* __restrict__ vW, int n) {
    __shared__ float sq[F][ABF];
    __shared__ float smu[3][F][ABF];
    __shared__ float sE[ABF][3];
    int f = threadIdx.x;
    int a0 = blockIdx.x * ABF;
#pragma unroll
    for (int a = 0; a < ABF; a++) {
        int at = a0 + a;
        int atc = (at < n) ? at : 0;
        sq[f][a] = g_q[atc*F + f];
#pragma unroll
        for (int kv = 0; kv < 3; kv++)
            smu[kv][f][a] = g_mu[(size_t)atc*F3 + kv*F + f] + g_dmu[(size_t)atc*F3 + kv*F + f];
    }
    if (f < ABF*3) {
        int a = f / 3, c = f % 3;
        int at = a0 + a;
        sE[a][c] = (at < n) ? g_E[at*3 + c] : 0.0f;
    }
    __syncthreads();
    ull acc[APF];
    {
        float bb = sb1[f];
        ull bb2 = pk2(bb, bb);
#pragma unroll
        for (int p = 0; p < APF; p++) acc[p] = bb2;
#pragma unroll 4
        for (int k = 0; k < F; k++) {
            float w = sW1[k*F + f];
            ull w2 = pk2(w, w);
            const ull* row = (const ull*)sq[k];
#pragma unroll
            for (int p = 0; p < APF; p++) acc[p] = ffma2(row[p], w2, acc[p]);
        }
    }
    __syncthreads();
#pragma unroll
    for (int p = 0; p < APF; p++) {
        float lo, hi; unpk2(acc[p], lo, hi);
        sq[f][2*p]   = silu_f(lo);
        sq[f][2*p+1] = silu_f(hi);
    }
    __syncthreads();
    ull as2[APF];
    {
        float bb = sb2[f];
        ull bb2 = pk2(bb, bb);
#pragma unroll
        for (int p = 0; p < APF; p++) as2[p] = bb2;
#pragma unroll 4
        for (int k = 0; k < F; k++) {
            float w = sW2[k*F + f];
            ull w2 = pk2(w, w);
            const ull* row = (const ull*)sq[k];
#pragma unroll
            for (int p = 0; p < APF; p++) as2[p] = ffma2(row[p], w2, as2[p]);
        }
    }
    ull av2[3][APF];
#pragma unroll
    for (int kv = 0; kv < 3; kv++)
#pragma unroll
        for (int p = 0; p < APF; p++) av2[kv][p] = 0ull;
#pragma unroll 2
    for (int c = 0; c < F; c++) {
        float w = vW[c*F + f];
        ull w2 = pk2(w, w);
#pragma unroll
        for (int kv = 0; kv < 3; kv++) {
            const ull* row = (const ull*)smu[kv][c];
#pragma unroll
            for (int p = 0; p < APF; p++) av2[kv][p] = ffma2(row[p], w2, av2[kv][p]);
        }
    }
#pragma unroll
    for (int p = 0; p < APF; p++) {
        float as_l, as_h; unpk2(as2[p], as_l, as_h);
        float a0l, a0h, a1l, a1h, a2l, a2h;
        unpk2(av2[0][p], a0l, a0h);
        unpk2(av2[1][p], a1l, a1h);
        unpk2(av2[2][p], a2l, a2h);
#pragma unroll
        for (int lane = 0; lane < 2; lane++) {
            int a = 2*p + lane;
            int at = a0 + a;
            if (at >= n) continue;
            float asv = lane ? as_h : as_l;
            float v0 = lane ? a0h : a0l;
            float v1 = lane ? a1h : a1l;
            float v2 = lane ? a2h : a2l;
            float E0 = sE[a][0], E1 = sE[a][1], E2 = sE[a][2];
            float dot = v0*E0 + v1*E1 + v2*E2;
            g_mu[(size_t)at*F3 + f]       = smu[0][f][a] + asv*E0 - dot*v0;
            g_mu[(size_t)at*F3 + F + f]   = smu[1][f][a] + asv*E1 - dot*v1;
            g_mu[(size_t)at*F3 + 2*F + f] = smu[2][f][a] + asv*E2 - dot*v2;
        }
    }
}

// ---------------- mixing (A=8) ----------------------------------------------
__global__ void __launch_bounds__(128) k_mix(
        const float* __restrict__ muW, const float* __restrict__ W1,
        const float* __restrict__ b1,  const float* __restrict__ W2,
        const float* __restrict__ b2,  int n) {
    __shared__ float smu[3][F][ABM];
    __shared__ float cs[2*F][ABM];
    int f = threadIdx.x;
    int a0 = blockIdx.x * ABM;
#pragma unroll
    for (int a = 0; a < ABM; a++) {
        int at = a0 + a;
        int atc = (at < n) ? at : 0;
        cs[f][a] = g_q[atc*F + f];
#pragma unroll
        for (int kv = 0; kv < 3; kv++)
            smu[kv][f][a] = g_mu[(size_t)atc*F3 + kv*F + f];
    }
    __syncthreads();
    ull Wc2[3][APM];
    ull sdot2[APM];
    {
        ull V2[3][APM];
#pragma unroll
        for (int kv = 0; kv < 3; kv++)
#pragma unroll
            for (int p = 0; p < APM; p++) { V2[kv][p] = 0ull; Wc2[kv][p] = 0ull; }
#pragma unroll 2
        for (int c = 0; c < F; c++) {
            float wv = muW[c*2*F + f];
            float ww = muW[c*2*F + F + f];
            ull wv2 = pk2(wv, wv);
            ull ww2 = pk2(ww, ww);
#pragma unroll
            for (int kv = 0; kv < 3; kv++) {
                const ull* row = (const ull*)smu[kv][c];
#pragma unroll
                for (int p = 0; p < APM; p++) {
                    ull m = row[p];
                    V2[kv][p]  = ffma2(m, wv2, V2[kv][p]);
                    Wc2[kv][p] = ffma2(m, ww2, Wc2[kv][p]);
                }
            }
        }
#pragma unroll
        for (int p = 0; p < APM; p++) {
            float v0l, v0h, v1l, v1h, v2l, v2h;
            unpk2(V2[0][p], v0l, v0h);
            unpk2(V2[1][p], v1l, v1h);
            unpk2(V2[2][p], v2l, v2h);
            float w0l, w0h, w1l, w1h, w2l, w2h;
            unpk2(Wc2[0][p], w0l, w0h);
            unpk2(Wc2[1][p], w1l, w1h);
            unpk2(Wc2[2][p], w2l, w2h);
            float vnl = sqrtf(v0l*v0l + v1l*v1l + v2l*v2l + 1e-8f);
            float vnh = sqrtf(v0h*v0h + v1h*v1h + v2h*v2h + 1e-8f);
            cs[F + f][2*p]   = vnl;
            cs[F + f][2*p+1] = vnh;
            sdot2[p] = pk2(v0l*w0l + v1l*w1l + v2l*w2l,
                           v0h*w0h + v1h*w1h + v2h*w2h);
        }
    }
    __syncthreads();
    ull acc[APM];
    {
        float bb = b1[f];
        ull bb2 = pk2(bb, bb);
#pragma unroll
        for (int p = 0; p < APM; p++) acc[p] = bb2;
#pragma unroll 4
        for (int k = 0; k < 2*F; k++) {
            float w = W1[k*F + f];
            ull w2 = pk2(w, w);
            const ull* row = (const ull*)cs[k];
#pragma unroll
            for (int p = 0; p < APM; p++) acc[p] = ffma2(row[p], w2, acc[p]);
        }
    }
    __syncthreads();
#pragma unroll
    for (int p = 0; p < APM; p++) {
        float lo, hi; unpk2(acc[p], lo, hi);
        cs[f][2*p]   = silu_f(lo);
        cs[f][2*p+1] = silu_f(hi);
    }
    __syncthreads();
    ull y0_2[APM];
#pragma unroll
    for (int c = 0; c < 3; c++) {
        float cb = b2[c*F + f];
        ull accY[APM];
        ull cb2 = pk2(cb, cb);
#pragma unroll
        for (int p = 0; p < APM; p++) accY[p] = cb2;
#pragma unroll 4
        for (int k = 0; k < F; k++) {
            float w = W2[k*F3 + c*F + f];
            ull w2 = pk2(w, w);
            const ull* row = (const ull*)cs[k];
#pragma unroll
            for (int p = 0; p < APM; p++) accY[p] = ffma2(row[p], w2, accY[p]);
        }
        if (c == 0) {
#pragma unroll
            for (int p = 0; p < APM; p++) y0_2[p] = accY[p];
        } else if (c == 1) {
#pragma unroll
            for (int p = 0; p < APM; p++) {
                float y1l, y1h; unpk2(accY[p], y1l, y1h);
                float w0l, w0h, w1l, w1h, w2l, w2h;
                unpk2(Wc2[0][p], w0l, w0h);
                unpk2(Wc2[1][p], w1l, w1h);
                unpk2(Wc2[2][p], w2l, w2h);
                int at = a0 + 2*p;
                if (at < n) {
                    g_mu[(size_t)at*F3 + f]       = smu[0][f][2*p] + y1l*w0l;
                    g_mu[(size_t)at*F3 + F + f]   = smu[1][f][2*p] + y1l*w1l;
                    g_mu[(size_t)at*F3 + 2*F + f] = smu[2][f][2*p] + y1l*w2l;
                }
                if (at + 1 < n) {
                    g_mu[(size_t)(at+1)*F3 + f]       = smu[0][f][2*p+1] + y1h*w0h;
                    g_mu[(size_t)(at+1)*F3 + F + f]   = smu[1][f][2*p+1] + y1h*w1h;
                    g_mu[(size_t)(at+1)*F3 + 2*F + f] = smu[2][f][2*p+1] + y1h*w2h;
                }
            }
        } else {
#pragma unroll
            for (int p = 0; p < APM; p++) {
                float y2l, y2h; unpk2(accY[p], y2l, y2h);
                float y0l, y0h; unpk2(y0_2[p], y0l, y0h);
                float sdl, sdh; unpk2(sdot2[p], sdl, sdh);
                int at = a0 + 2*p;
                if (at < n)     g_q[(size_t)at*F + f]     += y0l + y2l*sdl;
                if (at + 1 < n) g_q[(size_t)(at+1)*F + f] += y0h + y2h*sdh;
            }
        }
    }
}

// ---------------- pack output [N,4,F] ---------------------------------------
__global__ void k_pack(float* __restrict__ out, int n) {
    int i = blockIdx.x;
    int f = threadIdx.x;
    if (i >= n) return;
    out[i*4*F + f] = g_q[i*F + f];
#pragma unroll
    for (int kv = 0; kv < 3; kv++)
        out[i*4*F + (1+kv)*F + f] = g_mu[i*F3 + kv*F + f];
}

// ---------------- launch -----------------------------------------------------
extern "C" void kernel_launch(void* const* d_in, const int* in_sizes, int n_in,
                              void* d_out, int out_size) {
    const int*   zn      = (const int*)  d_in[0];
    const float* r_ij    = (const float*)d_in[1];
    const int*   idx_i   = (const int*)  d_in[2];
    const int*   idx_j   = (const int*)  d_in[3];
    const int*   idx_m   = (const int*)  d_in[4];
    const float* e_field = (const float*)d_in[5];
    const float* emb     = (const float*)d_in[6];
    const float* filt_W  = (const float*)d_in[7];
    const float* filt_b  = (const float*)d_in[8];
    const float* iW1     = (const float*)d_in[9];
    const float* ib1     = (const float*)d_in[10];
    const float* iW2     = (const float*)d_in[11];
    const float* ib2     = (const float*)d_in[12];
    const float* fsW1    = (const float*)d_in[13];
    const float* fsb1    = (const float*)d_in[14];
    const float* fsW2    = (const float*)d_in[15];
    const float* fsb2    = (const float*)d_in[16];
    const float* fvW     = (const float*)d_in[17];
    const float* mmuW    = (const float*)d_in[18];
    const float* mW1     = (const float*)d_in[19];
    const float* mb1     = (const float*)d_in[20];
    const float* mW2     = (const float*)d_in[21];
    const float* mb2     = (const float*)d_in[22];

    int n  = in_sizes[0];   // 10000
    int ne = in_sizes[2];   // 320000
    int nblkI = (n + ABI - 1) / ABI;
    int nblkF = (n + ABF - 1) / ABF;
    int nblkM = (n + ABM - 1) / ABM;

    k_init<<<n, F>>>(zn, idx_m, e_field, emb, n);
    k_edge<<<(ne + 255) / 256, 256>>>(r_ij, ne);
    k_tab<<<TT*(NK-1), F3>>>(filt_W, filt_b);
    k_zero<<<(n + 255) / 256, 256>>>(n);
    k_hist<<<(ne + 255) / 256, 256>>>(idx_i, ne);
    k_scan<<<1, 1024>>>(n);
    k_scatter<<<(ne + 255) / 256, 256>>>(idx_i, ne);

    for (int t = 0; t < TT; t++) {
        k_inter<<<nblkI, F>>>(iW1 + t*F*F, ib1 + t*F,
                              iW2 + t*F*F3, ib2 + t*F3, n);
        k_msg<<<n, F>>>(idx_j, t, n);
        k_field<<<nblkF, F>>>(fsW1 + t*F*F, fsb1 + t*F,
                              fsW2 + t*F*F, fsb2 + t*F,
                              fvW + t*F*F, n);
        k_mix<<<nblkM, F>>>(mmuW + t*F*2*F, mW1 + t*2*F*F, mb1 + t*F,
                            mW2 + t*F*F3, mb2 + t*F3, n);
    }
    k_pack<<<n, F>>>((float*)d_out, n);
}

// round 7
// speedup vs baseline: 1.2969x; 1.0326x over previous
#include <cuda_runtime.h>
#include <cuda_fp16.h>
#include <math.h>

#define NA 10000
#define NE 320000
#define F  128
#define F3 (3*F)
#define NRBF 20
#define TT 3
#define NK 2048          // table rows per t (pairs k=0..2046 used)
#define ABI 16
#define API (ABI/2)
#define ABF 8
#define APF (ABF/2)
#define ABM 8
#define APM (ABM/2)

typedef unsigned long long ull;

// ---------------- scratch (static device globals; no allocation) -------------
__device__ float g_q[NA*F];
__device__ float g_mu[NA*F3];
__device__ float g_dmu[NA*F3];
__device__ float g_E[NA*3];
__device__ float g_x[NA*F3];
__device__ __half2 g_tabP[TT*NK*F3]; // filter table pairs: (v[k],v[k+1]) per channel, fp16
__device__ float g_dir[NE*3];
__device__ int   g_k0[NE];
__device__ float g_fr[NE];
__device__ int   g_cnt[NA];
__device__ int   g_starts[NA+1];
__device__ int   g_cursor[NA];
__device__ int   g_perm[NE];

__device__ __forceinline__ float silu_f(float v) {
    return v * (1.0f / (1.0f + __expf(-v)));
}

// ---- packed f32x2 helpers ----
__device__ __forceinline__ ull pk2(float lo, float hi) {
    ull r; asm("mov.b64 %0, {%1,%2};" : "=l"(r) : "f"(lo), "f"(hi)); return r;
}
__device__ __forceinline__ void unpk2(ull v, float& lo, float& hi) {
    asm("mov.b64 {%0,%1}, %2;" : "=f"(lo), "=f"(hi) : "l"(v));
}
__device__ __forceinline__ ull ffma2(ull a, ull b, ull c) {
    ull d; asm("fma.rn.f32x2 %0, %1, %2, %3;" : "=l"(d) : "l"(a), "l"(b), "l"(c));
    return d;
}

// ---------------- init ------------------------------------------------------
__global__ void k_init(const int* __restrict__ zn, const int* __restrict__ idx_m,
                       const float* __restrict__ e_field, const float* __restrict__ emb,
                       int n) {
    int i = blockIdx.x;
    int f = threadIdx.x;
    if (i >= n) return;
    int z = zn[i];
    g_q[i*F + f] = emb[z*F + f];
    g_mu[i*F3 + f]       = 0.0f;
    g_mu[i*F3 + F + f]   = 0.0f;
    g_mu[i*F3 + 2*F + f] = 0.0f;
    if (f < 3) g_E[i*3 + f] = e_field[idx_m[i]*3 + f];
}

// ---------------- edge precompute: dir, table coords ------------------------
__global__ void k_edge(const float* __restrict__ r_ij, int ne) {
    int e = blockIdx.x * blockDim.x + threadIdx.x;
    if (e >= ne) return;
    float x0 = r_ij[e*3+0], x1 = r_ij[e*3+1], x2 = r_ij[e*3+2];
    float d = sqrtf(x0*x0 + x1*x1 + x2*x2);
    float inv = 1.0f / d;
    g_dir[e*3+0] = x0*inv;
    g_dir[e*3+1] = x1*inv;
    g_dir[e*3+2] = x2*inv;
    float u = d * ((float)(NK-1) / 5.0f);      // 2047/5
    u = fminf(u, (float)(NK-1));               // d>=5 -> u=2047 -> v[2047]=0
    int k0 = min((int)u, NK-2);
    g_k0[e] = k0;
    g_fr[e] = u - (float)k0;
}

// ---------------- filter table build ----------------------------------------
// block b: t = b/(NK-1), k = b%(NK-1); computes pair (knot k, knot k+1) for all 384 ch
__global__ void k_tab(const float* __restrict__ filt_W, const float* __restrict__ filt_b) {
    __shared__ float ph[2][NRBF];
    __shared__ float fcs[2];
    int b = blockIdx.x;
    int t = b / (NK-1);
    int k = b % (NK-1);
    int c = threadIdx.x;  // 0..383
    const float h = 5.0f / (float)(NK-1);
    const float w = 5.0f / 19.0f;
    if (c < 2*NRBF) {
        int s = c / NRBF, r = c % NRBF;
        float d = (float)(k + s) * h;
        float tt = (d - w * (float)r) / w;
        ph[s][r] = __expf(-0.5f * tt * tt);
    }
    if (c >= 2*NRBF && c < 2*NRBF + 2) {
        int s = c - 2*NRBF;
        int kk = k + s;
        float d = (float)kk * h;
        fcs[s] = (kk >= NK-1) ? 0.0f : 0.5f * (__cosf(d * 0.6283185307179586f) + 1.0f);
    }
    __syncthreads();
    float bb = filt_b[t*F3 + c];
    float a0 = bb, a1 = bb;
#pragma unroll
    for (int r = 0; r < NRBF; r++) {
        float wv = filt_W[r * (TT*F3) + t*F3 + c];
        a0 = fmaf(ph[0][r], wv, a0);
        a1 = fmaf(ph[1][r], wv, a1);
    }
    g_tabP[((size_t)(t*NK + k))*F3 + c] = __floats2half2_rn(a0 * fcs[0], a1 * fcs[1]);
}

// ---------------- counting sort of edges by idx_i ---------------------------
__global__ void k_zero(int n) {
    int i = blockIdx.x * blockDim.x + threadIdx.x;
    if (i < n) g_cnt[i] = 0;
}
__global__ void k_hist(const int* __restrict__ idx_i, int ne) {
    int e = blockIdx.x * blockDim.x + threadIdx.x;
    if (e < ne) atomicAdd(&g_cnt[idx_i[e]], 1);
}
__global__ void k_scan(int n) {
    __shared__ int ss[1024];
    int tid = threadIdx.x;
    int chunk = (n + 1023) >> 10;
    int beg = tid * chunk;
    int end = min(beg + chunk, n);
    int s = 0;
    for (int i = beg; i < end; i++) s += g_cnt[i];
    ss[tid] = s;
    __syncthreads();
    for (int off = 1; off < 1024; off <<= 1) {
        int v = (tid >= off) ? ss[tid - off] : 0;
        __syncthreads();
        ss[tid] += v;
        __syncthreads();
    }
    int base = (tid == 0) ? 0 : ss[tid - 1];
    for (int i = beg; i < end; i++) {
        g_starts[i] = base;
        g_cursor[i] = base;
        base += g_cnt[i];
    }
    if (tid == 1023) g_starts[n] = ss[1023];
}
__global__ void k_scatter(const int* __restrict__ idx_i, int ne) {
    int e = blockIdx.x * blockDim.x + threadIdx.x;
    if (e < ne) {
        int p = atomicAdd(&g_cursor[idx_i[e]], 1);
        g_perm[p] = e;
    }
}

// ---------------- inter: x = silu(q@W1+b1)@W2+b2  (A=16, f32x2) ------------
__global__ void __launch_bounds__(128) k_inter(
        const float* __restrict__ W1, const float* __restrict__ b1,
        const float* __restrict__ W2, const float* __restrict__ b2, int n) {
    __shared__ float sq[F][ABI];
    int f = threadIdx.x;
    int a0 = blockIdx.x * ABI;
#pragma unroll
    for (int a = 0; a < ABI; a++) {
        int at = a0 + a;
        int atc = (at < n) ? at : 0;
        sq[f][a] = g_q[atc*F + f];
    }
    __syncthreads();
    ull acc[API];
    {
        float bb = b1[f];
        ull bb2 = pk2(bb, bb);
#pragma unroll
        for (int p = 0; p < API; p++) acc[p] = bb2;
#pragma unroll 4
        for (int k = 0; k < F; k++) {
            float w = W1[k*F + f];
            ull w2 = pk2(w, w);
            const ull* row = (const ull*)sq[k];
#pragma unroll
            for (int p = 0; p < API; p++) acc[p] = ffma2(row[p], w2, acc[p]);
        }
    }
    __syncthreads();
#pragma unroll
    for (int p = 0; p < API; p++) {
        float lo, hi; unpk2(acc[p], lo, hi);
        sq[f][2*p]   = silu_f(lo);
        sq[f][2*p+1] = silu_f(hi);
    }
    __syncthreads();
#pragma unroll
    for (int c = 0; c < 3; c++) {
        float cb = b2[c*F + f];
        ull acc2[API];
        ull cb2 = pk2(cb, cb);
#pragma unroll
        for (int p = 0; p < API; p++) acc2[p] = cb2;
#pragma unroll 4
        for (int k = 0; k < F; k++) {
            float w = W2[k*F3 + c*F + f];
            ull w2 = pk2(w, w);
            const ull* row = (const ull*)sq[k];
#pragma unroll
            for (int p = 0; p < API; p++) acc2[p] = ffma2(row[p], w2, acc2[p]);
        }
#pragma unroll
        for (int p = 0; p < API; p++) {
            float lo, hi; unpk2(acc2[p], lo, hi);
            int at = a0 + 2*p;
            if (at < n)     g_x[(size_t)at*F3 + c*F + f]     = lo;
            if (at + 1 < n) g_x[(size_t)(at+1)*F3 + c*F + f] = hi;
        }
    }
}

// ---------------- message passing: fp16 table-interp filters ----------------
__global__ void __launch_bounds__(128) k_msg(
        const int* __restrict__ idx_j, int t, int n) {
    __shared__ int   sj[128], sk0[128];
    __shared__ float sfr[128], sd0[128], sd1[128], sd2[128];
    int i = blockIdx.x;
    int f = threadIdx.x;
    if (i >= n) return;
    const __half2* __restrict__ tabT = g_tabP + (size_t)t * NK * F3;
    int nb = g_starts[i], nend = g_starts[i+1];
    float dq = 0.0f, dm0 = 0.0f, dm1 = 0.0f, dm2 = 0.0f;

    for (int base = nb; base < nend; base += 128) {
        int cnt = min(128, nend - base);
        __syncthreads();
        if (f < cnt) {
            int e = g_perm[base + f];
            sj[f]  = idx_j[e];
            sk0[f] = g_k0[e];
            sfr[f] = g_fr[e];
            sd0[f] = g_dir[e*3+0];
            sd1[f] = g_dir[e*3+1];
            sd2[f] = g_dir[e*3+2];
        }
        __syncthreads();
        for (int k = 0; k < cnt; k++) {
            int j = sj[k];
            const __half2* tr = tabT + (size_t)sk0[k] * F3;   // warp-uniform row
            float fr = sfr[k];
            float2 vq = __half22float2(tr[f]);
            float2 vR = __half22float2(tr[F + f]);
            float2 vM = __half22float2(tr[2*F + f]);
            const float* xr = g_x  + (size_t)j * F3;
            const float* mr = g_mu + (size_t)j * F3;
            float xq = xr[f], xR = xr[F + f], xM = xr[2*F + f];
            float m0 = mr[f], m1 = mr[F + f], m2 = mr[2*F + f];

            float fq = fmaf(fr, vq.y - vq.x, vq.x);
            float fR = fmaf(fr, vR.y - vR.x, vR.x);
            float fM = fmaf(fr, vM.y - vM.x, vM.x);

            dq = fmaf(fq, xq, dq);
            float dR = fR * xR;
            float dM = fM * xM;
            dm0 = fmaf(dR, sd0[k], fmaf(dM, m0, dm0));
            dm1 = fmaf(dR, sd1[k], fmaf(dM, m1, dm1));
            dm2 = fmaf(dR, sd2[k], fmaf(dM, m2, dm2));
        }
    }
    g_q[i*F + f] += dq;
    g_dmu[i*F3 + f]       = dm0;
    g_dmu[i*F3 + F + f]   = dm1;
    g_dmu[i*F3 + 2*F + f] = dm2;
}

// ---------------- field interaction (A=8, folds dmu) ------------------------
__global__ void __launch_bounds__(128) k_field(
        const float* __restrict__ sW1, const float* __restrict__ sb1,
        const float* __restrict__ sW2, const float* __restrict__ sb2,
        const float* __restrict__ vW, int n) {
    __shared__ float sq[F][ABF];
    __shared__ float smu[3][F][ABF];
    __shared__ float sE[ABF][3];
    int f = threadIdx.x;
    int a0 = blockIdx.x * ABF;
#pragma unroll
    for (int a = 0; a < ABF; a++) {
        int at = a0 + a;
        int atc = (at < n) ? at : 0;
        sq[f][a] = g_q[atc*F + f];
#pragma unroll
        for (int kv = 0; kv < 3; kv++)
            smu[kv][f][a] = g_mu[(size_t)atc*F3 + kv*F + f] + g_dmu[(size_t)atc*F3 + kv*F + f];
    }
    if (f < ABF*3) {
        int a = f / 3, c = f % 3;
        int at = a0 + a;
        sE[a][c] = (at < n) ? g_E[at*3 + c] : 0.0f;
    }
    __syncthreads();
    ull acc[APF];
    {
        float bb = sb1[f];
        ull bb2 = pk2(bb, bb);
#pragma unroll
        for (int p = 0; p < APF; p++) acc[p] = bb2;
#pragma unroll 4
        for (int k = 0; k < F; k++) {
            float w = sW1[k*F + f];
            ull w2 = pk2(w, w);
            const ull* row = (const ull*)sq[k];
#pragma unroll
            for (int p = 0; p < APF; p++) acc[p] = ffma2(row[p], w2, acc[p]);
        }
    }
    __syncthreads();
#pragma unroll
    for (int p = 0; p < APF; p++) {
        float lo, hi; unpk2(acc[p], lo, hi);
        sq[f][2*p]   = silu_f(lo);
        sq[f][2*p+1] = silu_f(hi);
    }
    __syncthreads();
    ull as2[APF];
    {
        float bb = sb2[f];
        ull bb2 = pk2(bb, bb);
#pragma unroll
        for (int p = 0; p < APF; p++) as2[p] = bb2;
#pragma unroll 4
        for (int k = 0; k < F; k++) {
            float w = sW2[k*F + f];
            ull w2 = pk2(w, w);
            const ull* row = (const ull*)sq[k];
#pragma unroll
            for (int p = 0; p < APF; p++) as2[p] = ffma2(row[p], w2, as2[p]);
        }
    }
    ull av2[3][APF];
#pragma unroll
    for (int kv = 0; kv < 3; kv++)
#pragma unroll
        for (int p = 0; p < APF; p++) av2[kv][p] = 0ull;
#pragma unroll 2
    for (int c = 0; c < F; c++) {
        float w = vW[c*F + f];
        ull w2 = pk2(w, w);
#pragma unroll
        for (int kv = 0; kv < 3; kv++) {
            const ull* row = (const ull*)smu[kv][c];
#pragma unroll
            for (int p = 0; p < APF; p++) av2[kv][p] = ffma2(row[p], w2, av2[kv][p]);
        }
    }
#pragma unroll
    for (int p = 0; p < APF; p++) {
        float as_l, as_h; unpk2(as2[p], as_l, as_h);
        float a0l, a0h, a1l, a1h, a2l, a2h;
        unpk2(av2[0][p], a0l, a0h);
        unpk2(av2[1][p], a1l, a1h);
        unpk2(av2[2][p], a2l, a2h);
#pragma unroll
        for (int lane = 0; lane < 2; lane++) {
            int a = 2*p + lane;
            int at = a0 + a;
            if (at >= n) continue;
            float asv = lane ? as_h : as_l;
            float v0 = lane ? a0h : a0l;
            float v1 = lane ? a1h : a1l;
            float v2 = lane ? a2h : a2l;
            float E0 = sE[a][0], E1 = sE[a][1], E2 = sE[a][2];
            float dot = v0*E0 + v1*E1 + v2*E2;
            g_mu[(size_t)at*F3 + f]       = smu[0][f][a] + asv*E0 - dot*v0;
            g_mu[(size_t)at*F3 + F + f]   = smu[1][f][a] + asv*E1 - dot*v1;
            g_mu[(size_t)at*F3 + 2*F + f] = smu[2][f][a] + asv*E2 - dot*v2;
        }
    }
}

// ---------------- mixing (A=8) ----------------------------------------------
__global__ void __launch_bounds__(128) k_mix(
        const float* __restrict__ muW, const float* __restrict__ W1,
        const float* __restrict__ b1,  const float* __restrict__ W2,
        const float* __restrict__ b2,  int n) {
    __shared__ float smu[3][F][ABM];
    __shared__ float cs[2*F][ABM];
    int f = threadIdx.x;
    int a0 = blockIdx.x * ABM;
#pragma unroll
    for (int a = 0; a < ABM; a++) {
        int at = a0 + a;
        int atc = (at < n) ? at : 0;
        cs[f][a] = g_q[atc*F + f];
#pragma unroll
        for (int kv = 0; kv < 3; kv++)
            smu[kv][f][a] = g_mu[(size_t)atc*F3 + kv*F + f];
    }
    __syncthreads();
    ull Wc2[3][APM];
    ull sdot2[APM];
    {
        ull V2[3][APM];
#pragma unroll
        for (int kv = 0; kv < 3; kv++)
#pragma unroll
            for (int p = 0; p < APM; p++) { V2[kv][p] = 0ull; Wc2[kv][p] = 0ull; }
#pragma unroll 2
        for (int c = 0; c < F; c++) {
            float wv = muW[c*2*F + f];
            float ww = muW[c*2*F + F + f];
            ull wv2 = pk2(wv, wv);
            ull ww2 = pk2(ww, ww);
#pragma unroll
            for (int kv = 0; kv < 3; kv++) {
                const ull* row = (const ull*)smu[kv][c];
#pragma unroll
                for (int p = 0; p < APM; p++) {
                    ull m = row[p];
                    V2[kv][p]  = ffma2(m, wv2, V2[kv][p]);
                    Wc2[kv][p] = ffma2(m, ww2, Wc2[kv][p]);
                }
            }
        }
#pragma unroll
        for (int p = 0; p < APM; p++) {
            float v0l, v0h, v1l, v1h, v2l, v2h;
            unpk2(V2[0][p], v0l, v0h);
            unpk2(V2[1][p], v1l, v1h);
            unpk2(V2[2][p], v2l, v2h);
            float w0l, w0h, w1l, w1h, w2l, w2h;
            unpk2(Wc2[0][p], w0l, w0h);
            unpk2(Wc2[1][p], w1l, w1h);
            unpk2(Wc2[2][p], w2l, w2h);
            float vnl = sqrtf(v0l*v0l + v1l*v1l + v2l*v2l + 1e-8f);
            float vnh = sqrtf(v0h*v0h + v1h*v1h + v2h*v2h + 1e-8f);
            cs[F + f][2*p]   = vnl;
            cs[F + f][2*p+1] = vnh;
            sdot2[p] = pk2(v0l*w0l + v1l*w1l + v2l*w2l,
                           v0h*w0h + v1h*w1h + v2h*w2h);
        }
    }
    __syncthreads();
    ull acc[APM];
    {
        float bb = b1[f];
        ull bb2 = pk2(bb, bb);
#pragma unroll
        for (int p = 0; p < APM; p++) acc[p] = bb2;
#pragma unroll 4
        for (int k = 0; k < 2*F; k++) {
            float w = W1[k*F + f];
            ull w2 = pk2(w, w);
            const ull* row = (const ull*)cs[k];
#pragma unroll
            for (int p = 0; p < APM; p++) acc[p] = ffma2(row[p], w2, acc[p]);
        }
    }
    __syncthreads();
#pragma unroll
    for (int p = 0; p < APM; p++) {
        float lo, hi; unpk2(acc[p], lo, hi);
        cs[f][2*p]   = silu_f(lo);
        cs[f][2*p+1] = silu_f(hi);
    }
    __syncthreads();
    ull y0_2[APM];
#pragma unroll
    for (int c = 0; c < 3; c++) {
        float cb = b2[c*F + f];
        ull accY[APM];
        ull cb2 = pk2(cb, cb);
#pragma unroll
        for (int p = 0; p < APM; p++) accY[p] = cb2;
#pragma unroll 4
        for (int k = 0; k < F; k++) {
            float w = W2[k*F3 + c*F + f];
            ull w2 = pk2(w, w);
            const ull* row = (const ull*)cs[k];
#pragma unroll
            for (int p = 0; p < APM; p++) accY[p] = ffma2(row[p], w2, accY[p]);
        }
        if (c == 0) {
#pragma unroll
            for (int p = 0; p < APM; p++) y0_2[p] = accY[p];
        } else if (c == 1) {
#pragma unroll
            for (int p = 0; p < APM; p++) {
                float y1l, y1h; unpk2(accY[p], y1l, y1h);
                float w0l, w0h, w1l, w1h, w2l, w2h;
                unpk2(Wc2[0][p], w0l, w0h);
                unpk2(Wc2[1][p], w1l, w1h);
                unpk2(Wc2[2][p], w2l, w2h);
                int at = a0 + 2*p;
                if (at < n) {
                    g_mu[(size_t)at*F3 + f]       = smu[0][f][2*p] + y1l*w0l;
                    g_mu[(size_t)at*F3 + F + f]   = smu[1][f][2*p] + y1l*w1l;
                    g_mu[(size_t)at*F3 + 2*F + f] = smu[2][f][2*p] + y1l*w2l;
                }
                if (at + 1 < n) {
                    g_mu[(size_t)(at+1)*F3 + f]       = smu[0][f][2*p+1] + y1h*w0h;
                    g_mu[(size_t)(at+1)*F3 + F + f]   = smu[1][f][2*p+1] + y1h*w1h;
                    g_mu[(size_t)(at+1)*F3 + 2*F + f] = smu[2][f][2*p+1] + y1h*w2h;
                }
            }
        } else {
#pragma unroll
            for (int p = 0; p < APM; p++) {
                float y2l, y2h; unpk2(accY[p], y2l, y2h);
                float y0l, y0h; unpk2(y0_2[p], y0l, y0h);
                float sdl, sdh; unpk2(sdot2[p], sdl, sdh);
                int at = a0 + 2*p;
                if (at < n)     g_q[(size_t)at*F + f]     += y0l + y2l*sdl;
                if (at + 1 < n) g_q[(size_t)(at+1)*F + f] += y0h + y2h*sdh;
            }
        }
    }
}

// ---------------- pack output [N,4,F] ---------------------------------------
__global__ void k_pack(float* __restrict__ out, int n) {
    int i = blockIdx.x;
    int f = threadIdx.x;
    if (i >= n) return;
    out[i*4*F + f] = g_q[i*F + f];
#pragma unroll
    for (int kv = 0; kv < 3; kv++)
        out[i*4*F + (1+kv)*F + f] = g_mu[i*F3 + kv*F + f];
}

// ---------------- launch -----------------------------------------------------
extern "C" void kernel_launch(void* const* d_in, const int* in_sizes, int n_in,
                              void* d_out, int out_size) {
    const int*   zn      = (const int*)  d_in[0];
    const float* r_ij    = (const float*)d_in[1];
    const int*   idx_i   = (const int*)  d_in[2];
    const int*   idx_j   = (const int*)  d_in[3];
    const int*   idx_m   = (const int*)  d_in[4];
    const float* e_field = (const float*)d_in[5];
    const float* emb     = (const float*)d_in[6];
    const float* filt_W  = (const float*)d_in[7];
    const float* filt_b  = (const float*)d_in[8];
    const float* iW1     = (const float*)d_in[9];
    const float* ib1     = (const float*)d_in[10];
    const float* iW2     = (const float*)d_in[11];
    const float* ib2     = (const float*)d_in[12];
    const float* fsW1    = (const float*)d_in[13];
    const float* fsb1    = (const float*)d_in[14];
    const float* fsW2    = (const float*)d_in[15];
    const float* fsb2    = (const float*)d_in[16];
    const float* fvW     = (const float*)d_in[17];
    const float* mmuW    = (const float*)d_in[18];
    const float* mW1     = (const float*)d_in[19];
    const float* mb1     = (const float*)d_in[20];
    const float* mW2     = (const float*)d_in[21];
    const float* mb2     = (const float*)d_in[22];

    int n  = in_sizes[0];   // 10000
    int ne = in_sizes[2];   // 320000
    int nblkI = (n + ABI - 1) / ABI;
    int nblkF = (n + ABF - 1) / ABF;
    int nblkM = (n + ABM - 1) / ABM;

    k_init<<<n, F>>>(zn, idx_m, e_field, emb, n);
    k_edge<<<(ne + 255) / 256, 256>>>(r_ij, ne);
    k_tab<<<TT*(NK-1), F3>>>(filt_W, filt_b);
    k_zero<<<(n + 255) / 256, 256>>>(n);
    k_hist<<<(ne + 255) / 256, 256>>>(idx_i, ne);
    k_scan<<<1, 1024>>>(n);
    k_scatter<<<(ne + 255) / 256, 256>>>(idx_i, ne);

    for (int t = 0; t < TT; t++) {
        k_inter<<<nblkI, F>>>(iW1 + t*F*F, ib1 + t*F,
                              iW2 + t*F*F3, ib2 + t*F3, n);
        k_msg<<<n, F>>>(idx_j, t, n);
        k_field<<<nblkF, F>>>(fsW1 + t*F*F, fsb1 + t*F,
                              fsW2 + t*F*F, fsb2 + t*F,
                              fvW + t*F*F, n);
        k_mix<<<nblkM, F>>>(mmuW + t*F*2*F, mW1 + t*2*F*F, mb1 + t*F,
                            mW2 + t*F*F3, mb2 + t*F3, n);
    }
    k_pack<<<n, F>>>((float*)d_out, n);
}